// round 4
// baseline (speedup 1.0000x reference)
#include <cuda_runtime.h>
#include <math.h>

#define NMAX 16384
#define KNN  11      // neighbors kept (K=12 graph minus self)
#define TPB  128
#define S    8       // candidate-axis splits
#define TILE 2048    // NMAX / S

typedef unsigned long long u64;

// Static device scratch (no allocations allowed).
__device__ float4 g_pk[NMAX];                 // packed points: x,y,z,|p|^2 (for gather)
__device__ float4 g_xy[NMAX / 2];             // paired SoA: (x0,x1,y0,y1)
__device__ float4 g_zw[NMAX / 2];             // paired SoA: (z0,z1,w0,w1)
__device__ float  g_seed[NMAX];               // shifted seed threshold: seed_d2 - |q|^2
__device__ float  g_pd[S * KNN * NMAX];       // partial top-K shifted distances
__device__ int    g_pi[S * KNN * NMAX];       // partial top-K indices
__device__ int    g_fail_cnt;
__device__ int    g_fail[NMAX];

// ---- f32x2 packed helpers (sm_103a FFMA2 path) ----
__device__ __forceinline__ u64 pk2(float lo, float hi) {
    u64 r; asm("mov.b64 %0, {%1, %2};" : "=l"(r) : "f"(lo), "f"(hi)); return r;
}
__device__ __forceinline__ void upk2(float& lo, float& hi, u64 v) {
    asm("mov.b64 {%0, %1}, %2;" : "=f"(lo), "=f"(hi) : "l"(v));
}
__device__ __forceinline__ u64 fma2(u64 a, u64 b, u64 c) {
    u64 d; asm("fma.rn.f32x2 %0, %1, %2, %3;" : "=l"(d) : "l"(a), "l"(b), "l"(c)); return d;
}
__device__ __forceinline__ u64 mul2(u64 a, u64 b) {
    u64 d; asm("mul.rn.f32x2 %0, %1, %2;" : "=l"(d) : "l"(a), "l"(b)); return d;
}

__global__ void repack_kernel(const float* __restrict__ p, int n) {
    int i = blockIdx.x * blockDim.x + threadIdx.x;
    if (i == 0) g_fail_cnt = 0;
    if (i < n) {
        float x = p[3 * i + 0];
        float y = p[3 * i + 1];
        float z = p[3 * i + 2];
        float q2 = x * x + y * y + z * z;
        g_pk[i] = make_float4(x, y, z, q2);

        // paired SoA for the f32x2 hot loop
        float* fxy = (float*)&g_xy[i >> 1];
        float* fzw = (float*)&g_zw[i >> 1];
        int h = i & 1;
        fxy[0 + h] = x;  fxy[2 + h] = y;
        fzw[0 + h] = z;  fzw[2 + h] = q2;

        // Analytic 11-NN radius from local Gaussian density:
        // lambda = n*(2pi)^{-3/2}*exp(-q2/2);  r^3 = 33/(4pi*lambda)
        float lam = (float)n * 0.063493636f * __expf(-0.5f * q2);
        float f = 2.6260608f / lam;
        float r2 = cbrtf(f * f);                 // expected r11^2
        // Safety factor 1.8x in d^2; shifted by -q2 so hot loop compares
        // d' = |c|^2 - 2*q.c directly. Under-coverage repaired exactly later.
        g_seed[i] = 1.8f * r2 - q2;
    }
}

__device__ __forceinline__ void ins(float d, int j, float dist[KNN], int idxk[KNN]) {
    float dd = d; int jj = j;
#pragma unroll
    for (int k = 0; k < KNN; k++) {
        if (dd < dist[k]) {
            float td = dist[k]; int tj = idxk[k];
            dist[k] = dd; idxk[k] = jj;
            dd = td;      jj = tj;
        }
    }
}

// Phase 1: block = (128 queries) x (1 candidate split). Per-thread sorted
// top-11 of shifted distance d' = |c|^2 - 2*q.c, seeded analytically.
// Distances computed 2-at-a-time with fma.rn.f32x2.
__global__ __launch_bounds__(TPB) void knn_part_kernel(int n) {
    __shared__ ulonglong2 shxy[TILE / 2];   // (x-pair, y-pair)
    __shared__ ulonglong2 shzw[TILE / 2];   // (z-pair, w-pair)

    int qi    = blockIdx.x * TPB + threadIdx.x;
    int split = blockIdx.y;
    int cbeg  = split * TILE;
    int cend  = min(cbeg + TILE, n);

    int ql = min(qi, n - 1);
    float4 q = g_pk[ql];
    u64 qx2 = pk2(q.x, q.x);
    u64 qy2 = pk2(q.y, q.y);
    u64 qz2 = pk2(q.z, q.z);
    u64 n2  = pk2(-2.0f, -2.0f);
    float seed = g_seed[ql];

    float dist[KNN]; int idxk[KNN];
#pragma unroll
    for (int k = 0; k < KNN; k++) { dist[k] = seed; idxk[k] = -1; }

    // cooperative tile load (coalesced 16B)
    {
        const float4* sxy = g_xy + (cbeg >> 1);
        const float4* szw = g_zw + (cbeg >> 1);
        int npair = (cend - cbeg) >> 1;
        for (int t = threadIdx.x; t < TILE / 2; t += TPB) {
            if (t < npair) {
                float4 a = sxy[t];
                float4 b = szw[t];
                shxy[t] = make_ulonglong2(pk2(a.x, a.y), pk2(a.z, a.w));
                shzw[t] = make_ulonglong2(pk2(b.x, b.y), pk2(b.z, b.w));
            } else {
                shxy[t] = make_ulonglong2(0ULL, 0ULL);
                shzw[t] = make_ulonglong2(0ULL, pk2(3.0e38f, 3.0e38f));
            }
        }
    }
    __syncthreads();

    float worst = dist[KNN - 1];

    for (int j = 0; j < TILE; j += 8) {
        int jp = j >> 1;
        ulonglong2 xy0 = shxy[jp + 0];
        ulonglong2 xy1 = shxy[jp + 1];
        ulonglong2 xy2 = shxy[jp + 2];
        ulonglong2 xy3 = shxy[jp + 3];
        ulonglong2 zw0 = shzw[jp + 0];
        ulonglong2 zw1 = shzw[jp + 1];
        ulonglong2 zw2 = shzw[jp + 2];
        ulonglong2 zw3 = shzw[jp + 3];

        // d' = |c|^2 - 2*(q.c), two candidates per op
        u64 dp0 = fma2(n2, fma2(qz2, zw0.x, fma2(qy2, xy0.y, mul2(qx2, xy0.x))), zw0.y);
        u64 dp1 = fma2(n2, fma2(qz2, zw1.x, fma2(qy2, xy1.y, mul2(qx2, xy1.x))), zw1.y);
        u64 dp2 = fma2(n2, fma2(qz2, zw2.x, fma2(qy2, xy2.y, mul2(qx2, xy2.x))), zw2.y);
        u64 dp3 = fma2(n2, fma2(qz2, zw3.x, fma2(qy2, xy3.y, mul2(qx2, xy3.x))), zw3.y);

        float d0, d1, d2, d3, d4, d5, d6, d7;
        upk2(d0, d1, dp0);
        upk2(d2, d3, dp1);
        upk2(d4, d5, dp2);
        upk2(d6, d7, dp3);

        float m = fminf(fminf(fminf(d0, d1), fminf(d2, d3)),
                        fminf(fminf(d4, d5), fminf(d6, d7)));
        if (m < worst) {
            int g = cbeg + j;
            if (d0 < worst && g + 0 != qi) ins(d0, g + 0, dist, idxk);
            if (d1 < dist[KNN-1] && g + 1 != qi) ins(d1, g + 1, dist, idxk);
            if (d2 < dist[KNN-1] && g + 2 != qi) ins(d2, g + 2, dist, idxk);
            if (d3 < dist[KNN-1] && g + 3 != qi) ins(d3, g + 3, dist, idxk);
            if (d4 < dist[KNN-1] && g + 4 != qi) ins(d4, g + 4, dist, idxk);
            if (d5 < dist[KNN-1] && g + 5 != qi) ins(d5, g + 5, dist, idxk);
            if (d6 < dist[KNN-1] && g + 6 != qi) ins(d6, g + 6, dist, idxk);
            if (d7 < dist[KNN-1] && g + 7 != qi) ins(d7, g + 7, dist, idxk);
            worst = dist[KNN - 1];
        }
    }

    if (qi < n) {
#pragma unroll
        for (int k = 0; k < KNN; k++) {
            g_pd[(split * KNN + k) * NMAX + qi] = dist[k];
            g_pi[(split * KNN + k) * NMAX + qi] = idxk[k];
        }
    }
}

// Phase 2: merge S sorted partial lists; detect seed failures; apply
// closed-form GCNConv + mean-pool for complete queries.
__global__ __launch_bounds__(TPB) void merge_kernel(
    const float* __restrict__ W,
    const float* __restrict__ Bb,
    float* __restrict__ out,
    int n)
{
    int qi = blockIdx.x * TPB + threadIdx.x;
    if (qi >= n) return;

    float dist[KNN]; int idxk[KNN];
#pragma unroll
    for (int k = 0; k < KNN; k++) { dist[k] = 3.0e38f; idxk[k] = -1; }

    for (int s = 0; s < S; s++) {
#pragma unroll
        for (int k = 0; k < KNN; k++) {
            int o = (s * KNN + k) * NMAX + qi;
            float d = g_pd[o];
            int   j = g_pi[o];
            if (j < 0 || d >= dist[KNN - 1]) break;  // sorted ascending
            ins(d, j, dist, idxk);
        }
    }

    if (idxk[KNN - 1] < 0) {
        int slot = atomicAdd(&g_fail_cnt, 1);
        g_fail[slot] = qi;
        return;
    }

    float4 q = g_pk[qi];
    float w0 = W[0], w1 = W[1], w2 = W[2];

    float Ssum = 0.0f;
#pragma unroll
    for (int k = 0; k < KNN; k++) {
        float4 c = g_pk[idxk[k]];
        Ssum += fabsf(q.x - c.x) * w0 + fabsf(q.y - c.y) * w1 + fabsf(q.z - c.z) * w2;
    }

    float xw0 = q.x * w0 + q.y * w1 + q.z * w2;
    const float inv_s2 = 0.7071067811865475f;
    const float c0f = (1.0f + (float)KNN * inv_s2) / 12.0f;
    const float c1f = 1.0f / 24.0f;
    out[qi] = fmaf(c0f, xw0, fmaf(c1f, Ssum, Bb[0]));
}

// Phase 3: exact repair for queries the seed missed (expected ~8).
__global__ __launch_bounds__(32) void repair_kernel(
    const float* __restrict__ W,
    const float* __restrict__ Bb,
    float* __restrict__ out,
    int n)
{
    __shared__ float sd[32 * KNN];
    __shared__ int   si[32 * KNN];

    int lane = threadIdx.x;
    int nf = g_fail_cnt;

    for (int f = blockIdx.x; f < nf; f += gridDim.x) {
        int qi = g_fail[f];
        float4 q = g_pk[qi];
        float qx = q.x, qy = q.y, qz = q.z;

        float dist[KNN]; int idxk[KNN];
#pragma unroll
        for (int k = 0; k < KNN; k++) { dist[k] = 3.0e38f; idxk[k] = -1; }

        for (int j = lane; j < n; j += 32) {
            float4 c = g_pk[j];
            float d = fmaf(-2.0f, fmaf(qz, c.z, fmaf(qy, c.y, qx * c.x)), c.w);
            if (d < dist[KNN - 1] && j != qi) ins(d, j, dist, idxk);
        }
#pragma unroll
        for (int k = 0; k < KNN; k++) {
            sd[lane * KNN + k] = dist[k];
            si[lane * KNN + k] = idxk[k];
        }
        __syncwarp();

        if (lane == 0) {
            int ptr[32];
#pragma unroll
            for (int l = 0; l < 32; l++) ptr[l] = 0;
            float w0 = W[0], w1 = W[1], w2 = W[2];
            float Ssum = 0.0f;
            for (int k = 0; k < KNN; k++) {
                float best = 3.0e38f; int bl = 0;
                for (int l = 0; l < 32; l++) {
                    if (ptr[l] < KNN) {
                        float d = sd[l * KNN + ptr[l]];
                        if (d < best) { best = d; bl = l; }
                    }
                }
                int j = si[bl * KNN + ptr[bl]];
                ptr[bl]++;
                float4 c = g_pk[j];
                Ssum += fabsf(q.x - c.x) * w0 + fabsf(q.y - c.y) * w1
                      + fabsf(q.z - c.z) * w2;
            }
            float xw0 = q.x * w0 + q.y * w1 + q.z * w2;
            const float inv_s2 = 0.7071067811865475f;
            const float c0f = (1.0f + (float)KNN * inv_s2) / 12.0f;
            const float c1f = 1.0f / 24.0f;
            out[qi] = fmaf(c0f, xw0, fmaf(c1f, Ssum, Bb[0]));
        }
        __syncwarp();
    }
}

extern "C" void kernel_launch(void* const* d_in, const int* in_sizes, int n_in,
                              void* d_out, int out_size) {
    const float* p = (const float*)d_in[0];   // [2*8192*3] fp32
    const float* W = (const float*)d_in[1];   // [3]
    const float* b = (const float*)d_in[2];   // [1]
    float* out = (float*)d_out;               // [n,1] fp32

    int n = in_sizes[0] / 3;                  // 16384

    repack_kernel<<<(n + 255) / 256, 256>>>(p, n);

    dim3 grid((n + TPB - 1) / TPB, S);
    knn_part_kernel<<<grid, TPB>>>(n);

    merge_kernel<<<(n + TPB - 1) / TPB, TPB>>>(W, b, out, n);

    repair_kernel<<<128, 32>>>(W, b, out, n);
}

// round 5
// speedup vs baseline: 1.2580x; 1.2580x over previous
#include <cuda_runtime.h>
#include <math.h>

#define NMAX 16384
#define KNN  11      // neighbors kept (K=12 graph minus self)
#define TPB  128
#define S    8       // candidate-axis splits
#define TILE 2048    // NMAX / S
#define RTPB 256     // repair block size
#define RGRID 2048   // repair grid (block per failed query, grid-stride)

typedef unsigned long long u64;

// Static device scratch (no allocations allowed).
__device__ float4 g_pk[NMAX];                 // packed points: x,y,z,|p|^2 (for gather)
__device__ float4 g_xy[NMAX / 2];             // paired SoA: (x0,x1,y0,y1)
__device__ float4 g_zw[NMAX / 2];             // paired SoA: (z0,z1,w0,w1)
__device__ float  g_seed[NMAX];               // shifted seed threshold: seed_d2 - |q|^2
__device__ float  g_pd[S * KNN * NMAX];       // partial top-K shifted distances
__device__ int    g_pi[S * KNN * NMAX];       // partial top-K indices
__device__ int    g_fail_cnt;
__device__ int    g_fail[NMAX];

// ---- f32x2 packed helpers (sm_103a FFMA2 path) ----
__device__ __forceinline__ u64 pk2(float lo, float hi) {
    u64 r; asm("mov.b64 %0, {%1, %2};" : "=l"(r) : "f"(lo), "f"(hi)); return r;
}
__device__ __forceinline__ void upk2(float& lo, float& hi, u64 v) {
    asm("mov.b64 {%0, %1}, %2;" : "=f"(lo), "=f"(hi) : "l"(v));
}
__device__ __forceinline__ u64 fma2(u64 a, u64 b, u64 c) {
    u64 d; asm("fma.rn.f32x2 %0, %1, %2, %3;" : "=l"(d) : "l"(a), "l"(b), "l"(c)); return d;
}
__device__ __forceinline__ u64 mul2(u64 a, u64 b) {
    u64 d; asm("mul.rn.f32x2 %0, %1, %2;" : "=l"(d) : "l"(a), "l"(b)); return d;
}

__global__ void repack_kernel(const float* __restrict__ p, int n) {
    int i = blockIdx.x * blockDim.x + threadIdx.x;
    if (i == 0) g_fail_cnt = 0;
    if (i < n) {
        float x = p[3 * i + 0];
        float y = p[3 * i + 1];
        float z = p[3 * i + 2];
        float q2 = x * x + y * y + z * z;
        g_pk[i] = make_float4(x, y, z, q2);

        // paired SoA for the f32x2 hot loop
        float* fxy = (float*)&g_xy[i >> 1];
        float* fzw = (float*)&g_zw[i >> 1];
        int h = i & 1;
        fxy[0 + h] = x;  fxy[2 + h] = y;
        fzw[0 + h] = z;  fzw[2 + h] = q2;

        // Analytic 11-NN radius from local Gaussian density:
        // lambda = n*(2pi)^{-3/2}*exp(-q2/2);  r^3 = 33/(4pi*lambda)
        float lam = (float)n * 0.063493636f * __expf(-0.5f * q2);
        float f = 2.6260608f / lam;
        float r2 = cbrtf(f * f);                 // expected r11^2
        // Safety 1.8x keeps the hot loop's insert path rare; under-coverage
        // (a few % of queries) is repaired exactly by repair_kernel.
        g_seed[i] = 1.8f * r2 - q2;
    }
}

__device__ __forceinline__ void ins(float d, int j, float dist[KNN], int idxk[KNN]) {
    float dd = d; int jj = j;
#pragma unroll
    for (int k = 0; k < KNN; k++) {
        if (dd < dist[k]) {
            float td = dist[k]; int tj = idxk[k];
            dist[k] = dd; idxk[k] = jj;
            dd = td;      jj = tj;
        }
    }
}

// Phase 1: block = (128 queries) x (1 candidate split). Per-thread sorted
// top-11 of shifted distance d' = |c|^2 - 2*q.c, seeded analytically.
// Distances computed 2-at-a-time with fma.rn.f32x2.
__global__ __launch_bounds__(TPB) void knn_part_kernel(int n) {
    __shared__ ulonglong2 shxy[TILE / 2];   // (x-pair, y-pair)
    __shared__ ulonglong2 shzw[TILE / 2];   // (z-pair, w-pair)

    int qi    = blockIdx.x * TPB + threadIdx.x;
    int split = blockIdx.y;
    int cbeg  = split * TILE;
    int cend  = min(cbeg + TILE, n);

    int ql = min(qi, n - 1);
    float4 q = g_pk[ql];
    u64 qx2 = pk2(q.x, q.x);
    u64 qy2 = pk2(q.y, q.y);
    u64 qz2 = pk2(q.z, q.z);
    u64 n2  = pk2(-2.0f, -2.0f);
    float seed = g_seed[ql];

    float dist[KNN]; int idxk[KNN];
#pragma unroll
    for (int k = 0; k < KNN; k++) { dist[k] = seed; idxk[k] = -1; }

    // cooperative tile load (coalesced 16B)
    {
        const float4* sxy = g_xy + (cbeg >> 1);
        const float4* szw = g_zw + (cbeg >> 1);
        int npair = (cend - cbeg) >> 1;
        for (int t = threadIdx.x; t < TILE / 2; t += TPB) {
            if (t < npair) {
                float4 a = sxy[t];
                float4 b = szw[t];
                shxy[t] = make_ulonglong2(pk2(a.x, a.y), pk2(a.z, a.w));
                shzw[t] = make_ulonglong2(pk2(b.x, b.y), pk2(b.z, b.w));
            } else {
                shxy[t] = make_ulonglong2(0ULL, 0ULL);
                shzw[t] = make_ulonglong2(0ULL, pk2(3.0e38f, 3.0e38f));
            }
        }
    }
    __syncthreads();

    float worst = dist[KNN - 1];

    for (int j = 0; j < TILE; j += 8) {
        int jp = j >> 1;
        ulonglong2 xy0 = shxy[jp + 0];
        ulonglong2 xy1 = shxy[jp + 1];
        ulonglong2 xy2 = shxy[jp + 2];
        ulonglong2 xy3 = shxy[jp + 3];
        ulonglong2 zw0 = shzw[jp + 0];
        ulonglong2 zw1 = shzw[jp + 1];
        ulonglong2 zw2 = shzw[jp + 2];
        ulonglong2 zw3 = shzw[jp + 3];

        // d' = |c|^2 - 2*(q.c), two candidates per op
        u64 dp0 = fma2(n2, fma2(qz2, zw0.x, fma2(qy2, xy0.y, mul2(qx2, xy0.x))), zw0.y);
        u64 dp1 = fma2(n2, fma2(qz2, zw1.x, fma2(qy2, xy1.y, mul2(qx2, xy1.x))), zw1.y);
        u64 dp2 = fma2(n2, fma2(qz2, zw2.x, fma2(qy2, xy2.y, mul2(qx2, xy2.x))), zw2.y);
        u64 dp3 = fma2(n2, fma2(qz2, zw3.x, fma2(qy2, xy3.y, mul2(qx2, xy3.x))), zw3.y);

        float d0, d1, d2, d3, d4, d5, d6, d7;
        upk2(d0, d1, dp0);
        upk2(d2, d3, dp1);
        upk2(d4, d5, dp2);
        upk2(d6, d7, dp3);

        float m = fminf(fminf(fminf(d0, d1), fminf(d2, d3)),
                        fminf(fminf(d4, d5), fminf(d6, d7)));
        if (m < worst) {
            int g = cbeg + j;
            if (d0 < worst && g + 0 != qi) ins(d0, g + 0, dist, idxk);
            if (d1 < dist[KNN-1] && g + 1 != qi) ins(d1, g + 1, dist, idxk);
            if (d2 < dist[KNN-1] && g + 2 != qi) ins(d2, g + 2, dist, idxk);
            if (d3 < dist[KNN-1] && g + 3 != qi) ins(d3, g + 3, dist, idxk);
            if (d4 < dist[KNN-1] && g + 4 != qi) ins(d4, g + 4, dist, idxk);
            if (d5 < dist[KNN-1] && g + 5 != qi) ins(d5, g + 5, dist, idxk);
            if (d6 < dist[KNN-1] && g + 6 != qi) ins(d6, g + 6, dist, idxk);
            if (d7 < dist[KNN-1] && g + 7 != qi) ins(d7, g + 7, dist, idxk);
            worst = dist[KNN - 1];
        }
    }

    if (qi < n) {
#pragma unroll
        for (int k = 0; k < KNN; k++) {
            g_pd[(split * KNN + k) * NMAX + qi] = dist[k];
            g_pi[(split * KNN + k) * NMAX + qi] = idxk[k];
        }
    }
}

// Phase 2: merge S sorted partial lists; detect seed failures; apply
// closed-form GCNConv + mean-pool for complete queries.
__global__ __launch_bounds__(TPB) void merge_kernel(
    const float* __restrict__ W,
    const float* __restrict__ Bb,
    float* __restrict__ out,
    int n)
{
    int qi = blockIdx.x * TPB + threadIdx.x;
    if (qi >= n) return;

    float dist[KNN]; int idxk[KNN];
#pragma unroll
    for (int k = 0; k < KNN; k++) { dist[k] = 3.0e38f; idxk[k] = -1; }

    for (int s = 0; s < S; s++) {
#pragma unroll
        for (int k = 0; k < KNN; k++) {
            int o = (s * KNN + k) * NMAX + qi;
            float d = g_pd[o];
            int   j = g_pi[o];
            if (j < 0 || d >= dist[KNN - 1]) break;  // sorted ascending
            ins(d, j, dist, idxk);
        }
    }

    if (idxk[KNN - 1] < 0) {
        int slot = atomicAdd(&g_fail_cnt, 1);
        g_fail[slot] = qi;
        return;
    }

    float4 q = g_pk[qi];
    float w0 = W[0], w1 = W[1], w2 = W[2];

    float Ssum = 0.0f;
#pragma unroll
    for (int k = 0; k < KNN; k++) {
        float4 c = g_pk[idxk[k]];
        Ssum += fabsf(q.x - c.x) * w0 + fabsf(q.y - c.y) * w1 + fabsf(q.z - c.z) * w2;
    }

    float xw0 = q.x * w0 + q.y * w1 + q.z * w2;
    const float inv_s2 = 0.7071067811865475f;
    const float c0f = (1.0f + (float)KNN * inv_s2) / 12.0f;
    const float c1f = 1.0f / 24.0f;
    out[qi] = fmaf(c0f, xw0, fmaf(c1f, Ssum, Bb[0]));
}

// Phase 3: exact repair, block-per-failed-query (grid-stride).
// 256 threads scan 64 candidates each; sorted per-thread top-11 lists are
// merged by thread 0 with early break (lists sorted ascending).
__global__ __launch_bounds__(RTPB) void repair_kernel(
    const float* __restrict__ W,
    const float* __restrict__ Bb,
    float* __restrict__ out,
    int n)
{
    __shared__ float sd[RTPB * KNN];
    __shared__ int   si[RTPB * KNN];

    int tid = threadIdx.x;
    int nf = g_fail_cnt;

    for (int f = blockIdx.x; f < nf; f += gridDim.x) {
        int qi = g_fail[f];
        float4 q = g_pk[qi];
        float qx = q.x, qy = q.y, qz = q.z;

        float dist[KNN]; int idxk[KNN];
#pragma unroll
        for (int k = 0; k < KNN; k++) { dist[k] = 3.0e38f; idxk[k] = -1; }

        for (int j = tid; j < n; j += RTPB) {
            float4 c = g_pk[j];
            float d = fmaf(-2.0f, fmaf(qz, c.z, fmaf(qy, c.y, qx * c.x)), c.w);
            if (d < dist[KNN - 1] && j != qi) ins(d, j, dist, idxk);
        }
#pragma unroll
        for (int k = 0; k < KNN; k++) {
            sd[tid * KNN + k] = dist[k];
            si[tid * KNN + k] = idxk[k];
        }
        __syncthreads();

        if (tid == 0) {
            float md[KNN]; int mi[KNN];
#pragma unroll
            for (int k = 0; k < KNN; k++) { md[k] = 3.0e38f; mi[k] = 0; }
            for (int l = 0; l < RTPB; l++) {
#pragma unroll
                for (int k = 0; k < KNN; k++) {
                    float d = sd[l * KNN + k];
                    if (d >= md[KNN - 1]) break;   // list sorted ascending
                    int j = si[l * KNN + k];
                    if (j >= 0) ins(d, j, md, mi);
                }
            }
            float w0 = W[0], w1 = W[1], w2 = W[2];
            float Ssum = 0.0f;
#pragma unroll
            for (int k = 0; k < KNN; k++) {
                float4 c = g_pk[mi[k]];
                Ssum += fabsf(q.x - c.x) * w0 + fabsf(q.y - c.y) * w1
                      + fabsf(q.z - c.z) * w2;
            }
            float xw0 = q.x * w0 + q.y * w1 + q.z * w2;
            const float inv_s2 = 0.7071067811865475f;
            const float c0f = (1.0f + (float)KNN * inv_s2) / 12.0f;
            const float c1f = 1.0f / 24.0f;
            out[qi] = fmaf(c0f, xw0, fmaf(c1f, Ssum, Bb[0]));
        }
        __syncthreads();
    }
}

extern "C" void kernel_launch(void* const* d_in, const int* in_sizes, int n_in,
                              void* d_out, int out_size) {
    const float* p = (const float*)d_in[0];   // [2*8192*3] fp32
    const float* W = (const float*)d_in[1];   // [3]
    const float* b = (const float*)d_in[2];   // [1]
    float* out = (float*)d_out;               // [n,1] fp32

    int n = in_sizes[0] / 3;                  // 16384

    repack_kernel<<<(n + 255) / 256, 256>>>(p, n);

    dim3 grid((n + TPB - 1) / TPB, S);
    knn_part_kernel<<<grid, TPB>>>(n);

    merge_kernel<<<(n + TPB - 1) / TPB, TPB>>>(W, b, out, n);

    repair_kernel<<<RGRID, RTPB>>>(W, b, out, n);
}